// round 1
// baseline (speedup 1.0000x reference)
#include <cuda_runtime.h>

#define SQ 2048
#define BB 2
#define NH 12
#define DK 5
#define DM 64
#define DI 60
#define BHN (BB*NH)   // 24

// Scratch (device globals; no allocations allowed)
__device__ float g_q[BHN*SQ*DK];    // [B,H,S,DK], pre-scaled by 1/sqrt(DK)
__device__ float g_k[BHN*DK*SQ];    // [B,H,DK,S]
__device__ float g_v[BHN*DK*SQ];    // [B,H,DK,S]
__device__ float g_ctx[BB*SQ*DI];   // [B,S,60]

// ---------------------------------------------------------------------------
// Kernel 1: QKV projections. blockIdx.y selects Q/K/V. 64 rows per block.
// ---------------------------------------------------------------------------
__global__ __launch_bounds__(256) void proj_kernel(
    const float* __restrict__ Q, const float* __restrict__ K, const float* __restrict__ V,
    const float* __restrict__ Wq, const float* __restrict__ bq,
    const float* __restrict__ Wk, const float* __restrict__ bk,
    const float* __restrict__ Wv, const float* __restrict__ bv)
{
    __shared__ float Xs[64*DM];   // 16 KB
    __shared__ float Ws[DM*DI];   // 15.4 KB
    __shared__ float bs[DI];

    int mode = blockIdx.y;
    const float* X; const float* W; const float* bvec; float* outg;
    if (mode == 0)      { X = Q; W = Wq; bvec = bq; outg = g_q; }
    else if (mode == 1) { X = K; W = Wk; bvec = bk; outg = g_k; }
    else                { X = V; W = Wv; bvec = bv; outg = g_v; }

    int rowbase = blockIdx.x * 64;        // flattened (b*S + s)
    int tid = threadIdx.x;

    for (int idx = tid; idx < 64*DM; idx += 256) Xs[idx] = X[rowbase*DM + idx];
    for (int idx = tid; idx < DM*DI; idx += 256) Ws[idx] = W[idx];
    if (tid < DI) bs[tid] = bvec[tid];
    __syncthreads();

    if (tid < 240) {
        int o  = tid % DI;       // output channel 0..59
        int rb = tid / DI;       // 0..3
        int h = o / DK, d = o % DK;
        #pragma unroll 4
        for (int p = 0; p < 16; p++) {
            int r = rb + p*4;
            float acc = bs[o];
            #pragma unroll
            for (int m = 0; m < DM; m++) acc += Xs[r*DM + m] * Ws[m*DI + o];
            int rg = rowbase + r;
            int b = rg / SQ, s = rg % SQ;
            if (mode == 0) {
                // pre-fold softmax scale 1/sqrt(5) into q
                outg[((b*NH + h)*SQ + s)*DK + d] = acc * 0.44721359549995793f;
            } else {
                outg[((b*NH + h)*DK + d)*SQ + s] = acc;
            }
        }
    }
}

// ---------------------------------------------------------------------------
// Kernel 2: fused scores + bias + softmax + attn write + ctx accumulate.
// grid = (S/32 row tiles, B*H). 256 threads. Each thread owns 8 fixed key
// columns j = tid + i*256: K kept in registers, V in shared.
// ---------------------------------------------------------------------------
__global__ __launch_bounds__(256) void attn_kernel(
    const float* __restrict__ bias,
    const float* __restrict__ lam_p,
    float* __restrict__ attn_out)
{
    __shared__ float vs[DK*SQ];   // 40 KB
    __shared__ float red[8];
    __shared__ float wred[8*DK];

    int bh   = blockIdx.y;
    int row0 = blockIdx.x * 32;
    int tid  = threadIdx.x;
    int lane = tid & 31, wid = tid >> 5;
    float lam = lam_p[0];

    const float* kg = g_k + (size_t)bh * DK * SQ;
    const float* vg = g_v + (size_t)bh * DK * SQ;

    for (int idx = tid; idx < DK*SQ; idx += 256) vs[idx] = vg[idx];

    float kr[8][DK];
    #pragma unroll
    for (int i = 0; i < 8; i++) {
        int j = tid + i*256;
        #pragma unroll
        for (int d = 0; d < DK; d++) kr[i][d] = kg[d*SQ + j];
    }
    __syncthreads();

    int b = bh / NH, h = bh % NH;

    for (int r = 0; r < 32; r++) {
        int row = row0 + r;
        const float* qrow = g_q + ((size_t)bh*SQ + row)*DK;
        float q0 = qrow[0], q1 = qrow[1], q2 = qrow[2], q3 = qrow[3], q4 = qrow[4];
        const float* brow = bias     + ((size_t)bh*SQ + row)*(size_t)SQ;
        float*       arow = attn_out + ((size_t)bh*SQ + row)*(size_t)SQ;

        // scores + exp (no max-subtraction: scores bounded ~|7|, exp safe)
        float p[8];
        float lsum = 0.f;
        #pragma unroll
        for (int i = 0; i < 8; i++) {
            int j = tid + i*256;
            float s = lam * brow[j];
            s += q0*kr[i][0] + q1*kr[i][1] + q2*kr[i][2] + q3*kr[i][3] + q4*kr[i][4];
            float e = __expf(s);
            p[i] = e; lsum += e;
        }

        // block sum reduce
        #pragma unroll
        for (int off = 16; off > 0; off >>= 1) lsum += __shfl_xor_sync(0xffffffffu, lsum, off);
        if (lane == 0) red[wid] = lsum;
        __syncthreads();
        float tot = red[0]+red[1]+red[2]+red[3]+red[4]+red[5]+red[6]+red[7];
        float inv = __frcp_rn(tot);

        // normalized write + ctx accumulate
        float c0=0.f, c1=0.f, c2=0.f, c3=0.f, c4=0.f;
        #pragma unroll
        for (int i = 0; i < 8; i++) {
            int j = tid + i*256;
            float pp = p[i] * inv;
            arow[j] = pp;
            c0 += pp * vs[j];
            c1 += pp * vs[SQ   + j];
            c2 += pp * vs[2*SQ + j];
            c3 += pp * vs[3*SQ + j];
            c4 += pp * vs[4*SQ + j];
        }
        #pragma unroll
        for (int off = 16; off > 0; off >>= 1) {
            c0 += __shfl_xor_sync(0xffffffffu, c0, off);
            c1 += __shfl_xor_sync(0xffffffffu, c1, off);
            c2 += __shfl_xor_sync(0xffffffffu, c2, off);
            c3 += __shfl_xor_sync(0xffffffffu, c3, off);
            c4 += __shfl_xor_sync(0xffffffffu, c4, off);
        }
        if (lane == 0) {
            wred[wid*DK+0] = c0; wred[wid*DK+1] = c1; wred[wid*DK+2] = c2;
            wred[wid*DK+3] = c3; wred[wid*DK+4] = c4;
        }
        __syncthreads();
        if (tid < DK) {
            float cc = 0.f;
            #pragma unroll
            for (int w = 0; w < 8; w++) cc += wred[w*DK + tid];
            g_ctx[(b*SQ + row)*DI + h*DK + tid] = cc;
        }
        __syncthreads();
    }
}

// ---------------------------------------------------------------------------
// Kernel 3: out = residual + ctx @ Wo + bo. 64 rows per block, grid = 64.
// ---------------------------------------------------------------------------
__global__ __launch_bounds__(256) void out_kernel(
    const float* __restrict__ Qin, const float* __restrict__ Wo,
    const float* __restrict__ bo, float* __restrict__ out)
{
    __shared__ float Ws[DI*DM];   // 15.4 KB
    __shared__ float bs[DM];
    int tid = threadIdx.x;
    for (int idx = tid; idx < DI*DM; idx += 256) Ws[idx] = Wo[idx];
    if (tid < DM) bs[tid] = bo[tid];
    __syncthreads();

    int rowbase = blockIdx.x * 64;
    int m = tid % 64, rb = tid / 64;
    #pragma unroll 4
    for (int p = 0; p < 16; p++) {
        int r = rowbase + rb + p*4;
        const float* crow = g_ctx + r*DI;
        float acc = bs[m] + Qin[r*DM + m];
        #pragma unroll
        for (int o = 0; o < DI; o++) acc += crow[o] * Ws[o*DM + m];
        out[r*DM + m] = acc;
    }
}

// ---------------------------------------------------------------------------
extern "C" void kernel_launch(void* const* d_in, const int* in_sizes, int n_in,
                              void* d_out, int out_size)
{
    const float* Q    = (const float*)d_in[0];
    const float* K    = (const float*)d_in[1];
    const float* V    = (const float*)d_in[2];
    const float* bias = (const float*)d_in[3];
    const float* lam  = (const float*)d_in[4];
    const float* Wq   = (const float*)d_in[5];
    const float* bq   = (const float*)d_in[6];
    const float* Wk   = (const float*)d_in[7];
    const float* bk   = (const float*)d_in[8];
    const float* Wv   = (const float*)d_in[9];
    const float* bv   = (const float*)d_in[10];
    const float* Wo   = (const float*)d_in[11];
    const float* bo   = (const float*)d_in[12];

    float* out1 = (float*)d_out;                       // [B,S,64]
    float* attn = out1 + (size_t)BB*SQ*DM;             // [B,H,S,S]

    proj_kernel<<<dim3(BB*SQ/64, 3), 256>>>(Q, K, V, Wq, bq, Wk, bk, Wv, bv);
    attn_kernel<<<dim3(SQ/32, BHN), 256>>>(bias, lam, attn);
    out_kernel<<<BB*SQ/64, 256>>>(Q, Wo, bo, out1);
}

// round 2
// speedup vs baseline: 1.0478x; 1.0478x over previous
#include <cuda_runtime.h>

#define SQ 2048
#define BB 2
#define NH 12
#define DK 5
#define DM 64
#define DI 60
#define BHN (BB*NH)   // 24

// Scratch (device globals; no allocations allowed)
__device__ float g_q[BHN*SQ*DK];    // [B,H,S,DK], pre-scaled by 1/sqrt(DK)
__device__ float g_k[BHN*DK*SQ];    // [B,H,DK,S]
__device__ float g_v[BHN*DK*SQ];    // [B,H,DK,S]
__device__ float g_ctx[BB*SQ*DI];   // [B,S,60]

// ---------------------------------------------------------------------------
// Kernel 1: QKV projections, warp-per-row. 16 rows per block, grid (256, 3).
// Lane computes channels {lane, lane+32}. Conflict-free LDS, low regs.
// ---------------------------------------------------------------------------
__global__ __launch_bounds__(256) void proj_kernel(
    const float* __restrict__ Q, const float* __restrict__ K, const float* __restrict__ V,
    const float* __restrict__ Wq, const float* __restrict__ bq,
    const float* __restrict__ Wk, const float* __restrict__ bk,
    const float* __restrict__ Wv, const float* __restrict__ bv)
{
    __shared__ float Ws[DM*DI];   // 15.4 KB
    __shared__ float bs[DI];
    __shared__ float Xs[16][DM];  // 4 KB

    int mode = blockIdx.y;
    const float* X; const float* W; const float* bvec;
    if (mode == 0)      { X = Q; W = Wq; bvec = bq; }
    else if (mode == 1) { X = K; W = Wk; bvec = bk; }
    else                { X = V; W = Wv; bvec = bv; }

    int rowbase = blockIdx.x * 16;
    int tid = threadIdx.x;

    for (int idx = tid; idx < DM*DI; idx += 256) Ws[idx] = W[idx];
    for (int idx = tid; idx < 16*DM; idx += 256) Xs[idx >> 6][idx & 63] = X[rowbase*DM + idx];
    if (tid < DI) bs[tid] = bvec[tid];
    __syncthreads();

    int w = tid >> 5, lane = tid & 31;
    int o2  = lane + 32;
    int o2c = (o2 < DI) ? o2 : 0;   // clamped (result discarded for lane>=28)

    #pragma unroll
    for (int rr = 0; rr < 2; rr++) {
        int r = w + rr*8;
        float acc1 = bs[lane];
        float acc2 = bs[o2c];
        #pragma unroll 8
        for (int m = 0; m < DM; m++) {
            float x = Xs[r][m];                    // broadcast
            acc1 = fmaf(x, Ws[m*DI + lane], acc1); // conflict-free
            acc2 = fmaf(x, Ws[m*DI + o2c],  acc2);
        }
        int rg = rowbase + r;
        int b = rg >> 11, s = rg & (SQ-1);
        {
            int h = lane / DK, d = lane - h*DK;
            if (mode == 0)
                g_q[((b*NH+h)*SQ + s)*DK + d] = acc1 * 0.44721359549995793f;
            else if (mode == 1)
                g_k[((b*NH+h)*DK + d)*SQ + s] = acc1;
            else
                g_v[((b*NH+h)*DK + d)*SQ + s] = acc1;
        }
        if (o2 < DI) {
            int h = o2 / DK, d = o2 - h*DK;
            if (mode == 0)
                g_q[((b*NH+h)*SQ + s)*DK + d] = acc2 * 0.44721359549995793f;
            else if (mode == 1)
                g_k[((b*NH+h)*DK + d)*SQ + s] = acc2;
            else
                g_v[((b*NH+h)*DK + d)*SQ + s] = acc2;
        }
    }
}

// ---------------------------------------------------------------------------
// Kernel 2: fused scores + bias + softmax + attn write + ctx.
// grid (32, 24), 512 threads. Thread owns 4 consecutive cols (float4 I/O).
// K,V in registers. 2 rows per iter, ONE barrier per pair (parity-buffered
// reductions), bias prefetched across the barrier, ctx drain deferred 1 pair.
// ---------------------------------------------------------------------------
__global__ __launch_bounds__(512, 1) void attn_kernel(
    const float* __restrict__ bias,
    const float* __restrict__ lam_p,
    float* __restrict__ attn_out)
{
    __shared__ __align__(16) float red[2][2][16];   // [parity][row01][warp]
    __shared__ float wred[2][2][16][5];             // [parity][row01][warp][d]

    int bh   = blockIdx.y;
    int row0 = blockIdx.x * 64;
    int tid  = threadIdx.x;
    int lane = tid & 31, wid = tid >> 5;
    float lam = lam_p[0];

    const float* kg = g_k + (size_t)bh * DK * SQ;
    const float* vg = g_v + (size_t)bh * DK * SQ;
    const float* qg = g_q + ((size_t)bh*SQ + row0) * DK;
    int b = bh / NH, h = bh % NH;

    int j4 = tid * 4;
    float krr[DK][4], vrr[DK][4];
    #pragma unroll
    for (int d = 0; d < DK; d++) {
        float4 t = *(const float4*)(kg + d*SQ + j4);
        krr[d][0]=t.x; krr[d][1]=t.y; krr[d][2]=t.z; krr[d][3]=t.w;
        float4 u = *(const float4*)(vg + d*SQ + j4);
        vrr[d][0]=u.x; vrr[d][1]=u.y; vrr[d][2]=u.z; vrr[d][3]=u.w;
    }

    const float* bbase = bias     + ((size_t)bh*SQ + row0)*(size_t)SQ;
    float*       abase = attn_out + ((size_t)bh*SQ + row0)*(size_t)SQ;

    float bc0[4], bc1[4];
    {
        float4 t = __ldcs((const float4*)(bbase + j4));
        bc0[0]=t.x; bc0[1]=t.y; bc0[2]=t.z; bc0[3]=t.w;
        float4 u = __ldcs((const float4*)(bbase + SQ + j4));
        bc1[0]=u.x; bc1[1]=u.y; bc1[2]=u.z; bc1[3]=u.w;
    }

    for (int pair = 0; pair < 32; pair++) {
        int par = pair & 1;
        int r0  = pair * 2;
        const float* qp = qg + r0*DK;
        float q00=qp[0], q01=qp[1], q02=qp[2], q03=qp[3], q04=qp[4];
        float q10=qp[5], q11=qp[6], q12=qp[7], q13=qp[8], q14=qp[9];

        float e0[4], e1[4], ls0 = 0.f, ls1 = 0.f;
        #pragma unroll
        for (int i = 0; i < 4; i++) {
            float d0 = q00*krr[0][i];
            d0 = fmaf(q01,krr[1][i],d0); d0 = fmaf(q02,krr[2][i],d0);
            d0 = fmaf(q03,krr[3][i],d0); d0 = fmaf(q04,krr[4][i],d0);
            float s0 = fmaf(lam, bc0[i], d0);
            float d1 = q10*krr[0][i];
            d1 = fmaf(q11,krr[1][i],d1); d1 = fmaf(q12,krr[2][i],d1);
            d1 = fmaf(q13,krr[3][i],d1); d1 = fmaf(q14,krr[4][i],d1);
            float s1 = fmaf(lam, bc1[i], d1);
            e0[i] = __expf(s0); e1[i] = __expf(s1);
            ls0 += e0[i]; ls1 += e1[i];
        }

        // Prefetch next pair's bias BEFORE the barrier (hides DRAM latency).
        {
            int nr0 = (pair < 31) ? (r0 + 2) : r0;
            const float* bn = bbase + (size_t)nr0 * SQ;
            float4 t = __ldcs((const float4*)(bn + j4));
            bc0[0]=t.x; bc0[1]=t.y; bc0[2]=t.z; bc0[3]=t.w;
            float4 u = __ldcs((const float4*)(bn + SQ + j4));
            bc1[0]=u.x; bc1[1]=u.y; bc1[2]=u.z; bc1[3]=u.w;
        }

        #pragma unroll
        for (int off = 16; off; off >>= 1) {
            ls0 += __shfl_xor_sync(0xffffffffu, ls0, off);
            ls1 += __shfl_xor_sync(0xffffffffu, ls1, off);
        }
        if (lane == 0) { red[par][0][wid] = ls0; red[par][1][wid] = ls1; }
        __syncthreads();   // the ONLY barrier per pair

        // Deferred ctx drain of previous pair (no extra barrier needed).
        if (pair > 0 && tid < 10) {
            int rp = tid / 5, d = tid - rp*5;
            float cc = 0.f;
            #pragma unroll
            for (int w2 = 0; w2 < 16; w2++) cc += wred[par^1][rp][w2][d];
            int row = row0 + r0 - 2 + rp;
            g_ctx[((size_t)b*SQ + row)*DI + h*DK + d] = cc;
        }

        float tot0, tot1;
        {
            const float4* p0 = (const float4*)red[par][0];
            float4 a=p0[0], bb4=p0[1], c=p0[2], dd=p0[3];
            tot0 = ((a.x+a.y)+(a.z+a.w)) + ((bb4.x+bb4.y)+(bb4.z+bb4.w))
                 + ((c.x+c.y)+(c.z+c.w)) + ((dd.x+dd.y)+(dd.z+dd.w));
            const float4* p1 = (const float4*)red[par][1];
            float4 a1=p1[0], b1=p1[1], c1=p1[2], d1=p1[3];
            tot1 = ((a1.x+a1.y)+(a1.z+a1.w)) + ((b1.x+b1.y)+(b1.z+b1.w))
                 + ((c1.x+c1.y)+(c1.z+c1.w)) + ((d1.x+d1.y)+(d1.z+d1.w));
        }
        float inv0 = __frcp_rn(tot0), inv1 = __frcp_rn(tot1);

        float c00=0,c01=0,c02=0,c03=0,c04=0;
        float c10=0,c11=0,c12=0,c13=0,c14=0;
        float p0a[4], p1a[4];
        #pragma unroll
        for (int i = 0; i < 4; i++) {
            float p0 = e0[i]*inv0, p1 = e1[i]*inv1;
            p0a[i] = p0; p1a[i] = p1;
            c00=fmaf(p0,vrr[0][i],c00); c01=fmaf(p0,vrr[1][i],c01);
            c02=fmaf(p0,vrr[2][i],c02); c03=fmaf(p0,vrr[3][i],c03);
            c04=fmaf(p0,vrr[4][i],c04);
            c10=fmaf(p1,vrr[0][i],c10); c11=fmaf(p1,vrr[1][i],c11);
            c12=fmaf(p1,vrr[2][i],c12); c13=fmaf(p1,vrr[3][i],c13);
            c14=fmaf(p1,vrr[4][i],c14);
        }
        __stcs((float4*)(abase + (size_t)r0*SQ + j4),
               make_float4(p0a[0], p0a[1], p0a[2], p0a[3]));
        __stcs((float4*)(abase + (size_t)(r0+1)*SQ + j4),
               make_float4(p1a[0], p1a[1], p1a[2], p1a[3]));

        #pragma unroll
        for (int off = 16; off; off >>= 1) {
            c00 += __shfl_xor_sync(0xffffffffu,c00,off);
            c01 += __shfl_xor_sync(0xffffffffu,c01,off);
            c02 += __shfl_xor_sync(0xffffffffu,c02,off);
            c03 += __shfl_xor_sync(0xffffffffu,c03,off);
            c04 += __shfl_xor_sync(0xffffffffu,c04,off);
            c10 += __shfl_xor_sync(0xffffffffu,c10,off);
            c11 += __shfl_xor_sync(0xffffffffu,c11,off);
            c12 += __shfl_xor_sync(0xffffffffu,c12,off);
            c13 += __shfl_xor_sync(0xffffffffu,c13,off);
            c14 += __shfl_xor_sync(0xffffffffu,c14,off);
        }
        if (lane == 0) {
            wred[par][0][wid][0]=c00; wred[par][0][wid][1]=c01;
            wred[par][0][wid][2]=c02; wred[par][0][wid][3]=c03;
            wred[par][0][wid][4]=c04;
            wred[par][1][wid][0]=c10; wred[par][1][wid][1]=c11;
            wred[par][1][wid][2]=c12; wred[par][1][wid][3]=c13;
            wred[par][1][wid][4]=c14;
        }
    }
    __syncthreads();
    if (tid < 10) {   // drain last pair (pair=31 -> parity 1)
        int rp = tid / 5, d = tid - rp*5;
        float cc = 0.f;
        #pragma unroll
        for (int w2 = 0; w2 < 16; w2++) cc += wred[1][rp][w2][d];
        int row = row0 + 62 + rp;
        g_ctx[((size_t)b*SQ + row)*DI + h*DK + d] = cc;
    }
}

// ---------------------------------------------------------------------------
// Kernel 3: out = residual + ctx @ Wo + bo. Warp-per-row, 16 rows/block.
// ---------------------------------------------------------------------------
__global__ __launch_bounds__(256) void out_kernel(
    const float* __restrict__ Qin, const float* __restrict__ Wo,
    const float* __restrict__ bo, float* __restrict__ out)
{
    __shared__ float Ws[DI*DM];   // 15.4 KB
    __shared__ float bs[DM];
    __shared__ float Cs[16][DI];  // 3.84 KB
    int tid = threadIdx.x;
    int rowbase = blockIdx.x * 16;
    for (int idx = tid; idx < DI*DM; idx += 256) Ws[idx] = Wo[idx];
    if (tid < DM) bs[tid] = bo[tid];
    for (int idx = tid; idx < 16*DI; idx += 256) Cs[idx/DI][idx%DI] = g_ctx[rowbase*DI + idx];
    __syncthreads();

    int w = tid >> 5, lane = tid & 31;
    #pragma unroll
    for (int rr = 0; rr < 2; rr++) {
        int r = w + rr*8;
        int rg = rowbase + r;
        float acc1 = bs[lane]      + Qin[rg*DM + lane];
        float acc2 = bs[lane + 32] + Qin[rg*DM + lane + 32];
        #pragma unroll 10
        for (int o = 0; o < DI; o++) {
            float c = Cs[r][o];                      // broadcast
            acc1 = fmaf(c, Ws[o*DM + lane],      acc1);
            acc2 = fmaf(c, Ws[o*DM + lane + 32], acc2);
        }
        out[rg*DM + lane]      = acc1;
        out[rg*DM + lane + 32] = acc2;
    }
}

// ---------------------------------------------------------------------------
extern "C" void kernel_launch(void* const* d_in, const int* in_sizes, int n_in,
                              void* d_out, int out_size)
{
    const float* Q    = (const float*)d_in[0];
    const float* K    = (const float*)d_in[1];
    const float* V    = (const float*)d_in[2];
    const float* bias = (const float*)d_in[3];
    const float* lam  = (const float*)d_in[4];
    const float* Wq   = (const float*)d_in[5];
    const float* bq   = (const float*)d_in[6];
    const float* Wk   = (const float*)d_in[7];
    const float* bk   = (const float*)d_in[8];
    const float* Wv   = (const float*)d_in[9];
    const float* bv   = (const float*)d_in[10];
    const float* Wo   = (const float*)d_in[11];
    const float* bo   = (const float*)d_in[12];

    float* out1 = (float*)d_out;                 // [B,S,64]
    float* attn = out1 + (size_t)BB*SQ*DM;       // [B,H,S,S]

    proj_kernel<<<dim3(BB*SQ/16, 3), 256>>>(Q, K, V, Wq, bq, Wk, bk, Wv, bv);
    attn_kernel<<<dim3(SQ/64, BHN), 512>>>(bias, lam, attn);
    out_kernel<<<BB*SQ/16, 256>>>(Q, Wo, bo, out1);
}

// round 8
// speedup vs baseline: 1.5008x; 1.4323x over previous
#include <cuda_runtime.h>

#define SQ 2048
#define BB 2
#define NH 12
#define DK 5
#define DM 64
#define DI 60
#define BHN (BB*NH)   // 24

typedef unsigned long long ull;

__device__ __forceinline__ ull fma2(ull a, ull b, ull c){ ull d; asm("fma.rn.f32x2 %0,%1,%2,%3;":"=l"(d):"l"(a),"l"(b),"l"(c)); return d; }
__device__ __forceinline__ ull add2(ull a, ull b){ ull d; asm("add.rn.f32x2 %0,%1,%2;":"=l"(d):"l"(a),"l"(b)); return d; }
__device__ __forceinline__ ull mul2(ull a, ull b){ ull d; asm("mul.rn.f32x2 %0,%1,%2;":"=l"(d):"l"(a),"l"(b)); return d; }
__device__ __forceinline__ ull pack2(float lo, float hi){ ull d; asm("mov.b64 %0,{%1,%2};":"=l"(d):"f"(lo),"f"(hi)); return d; }
__device__ __forceinline__ void unpack2(ull v, float& lo, float& hi){ asm("mov.b64 {%0,%1},%2;":"=f"(lo),"=f"(hi):"l"(v)); }
__device__ __forceinline__ float ex2a(float x){ float y; asm("ex2.approx.f32 %0,%1;":"=f"(y):"f"(x)); return y; }
__device__ __forceinline__ float rcpa(float x){ float y; asm("rcp.approx.f32 %0,%1;":"=f"(y):"f"(x)); return y; }
__device__ __forceinline__ void ldcs2(const float* p, ull& a, ull& b){ asm("ld.global.cs.v2.b64 {%0,%1},[%2];":"=l"(a),"=l"(b):"l"(p)); }
__device__ __forceinline__ void stcs2(float* p, ull a, ull b){ asm("st.global.cs.v2.b64 [%0],{%1,%2};"::"l"(p),"l"(a),"l"(b):"memory"); }

// Scratch (device globals; no allocations allowed)
__device__ float g_q[BHN*SQ*DK];    // [B,H,S,DK], pre-scaled by log2e/sqrt(DK)
__device__ float g_k[BHN*DK*SQ];    // [B,H,DK,S]
__device__ float g_v[BHN*DK*SQ];    // [B,H,DK,S]
__device__ float g_ctx[BB*SQ*DI];   // [B,S,60]

// ---------------------------------------------------------------------------
// Kernel 1: QKV projections, warp-per-row. 64 rows/block, 512 threads,
// grid (64, 3). Lane computes channels {lane, lane+32}.
// ---------------------------------------------------------------------------
__global__ __launch_bounds__(512) void proj_kernel(
    const float* __restrict__ Q, const float* __restrict__ K, const float* __restrict__ V,
    const float* __restrict__ Wq, const float* __restrict__ bq,
    const float* __restrict__ Wk, const float* __restrict__ bk,
    const float* __restrict__ Wv, const float* __restrict__ bv)
{
    __shared__ float Ws[DM*DI];   // 15.4 KB
    __shared__ float bs[DI];
    __shared__ float Xs[64][DM];  // 16 KB

    int mode = blockIdx.y;
    const float* X; const float* W; const float* bvec;
    if (mode == 0)      { X = Q; W = Wq; bvec = bq; }
    else if (mode == 1) { X = K; W = Wk; bvec = bk; }
    else                { X = V; W = Wv; bvec = bv; }

    int rowbase = blockIdx.x * 64;
    int tid = threadIdx.x;

    for (int idx = tid; idx < DM*DI; idx += 512) Ws[idx] = W[idx];
    for (int idx = tid; idx < 1024; idx += 512)
        ((float4*)Xs)[idx] = ((const float4*)(X + rowbase*DM))[idx];
    if (tid < DI) bs[tid] = bvec[tid];
    __syncthreads();

    int w = tid >> 5, lane = tid & 31;
    int o2  = lane + 32;
    int o2c = (o2 < DI) ? o2 : 0;
    const float SCQ = 0.44721359549995793f * 1.4426950408889634f; // fold log2e

    #pragma unroll
    for (int rr = 0; rr < 4; rr++) {
        int r = w + rr*16;
        float acc1 = bs[lane];
        float acc2 = bs[o2c];
        #pragma unroll 8
        for (int m = 0; m < DM; m++) {
            float x = Xs[r][m];
            acc1 = fmaf(x, Ws[m*DI + lane], acc1);
            acc2 = fmaf(x, Ws[m*DI + o2c],  acc2);
        }
        int rg = rowbase + r;
        int b = rg >> 11, s = rg & (SQ-1);
        {
            int h = lane / DK, d = lane - h*DK;
            if (mode == 0)      g_q[((b*NH+h)*SQ + s)*DK + d] = acc1 * SCQ;
            else if (mode == 1) g_k[((b*NH+h)*DK + d)*SQ + s] = acc1;
            else                g_v[((b*NH+h)*DK + d)*SQ + s] = acc1;
        }
        if (o2 < DI) {
            int h = o2 / DK, d = o2 - h*DK;
            if (mode == 0)      g_q[((b*NH+h)*SQ + s)*DK + d] = acc2 * SCQ;
            else if (mode == 1) g_k[((b*NH+h)*DK + d)*SQ + s] = acc2;
            else                g_v[((b*NH+h)*DK + d)*SQ + s] = acc2;
        }
    }
}

// ---------------------------------------------------------------------------
// Kernel 2: fused scores + bias + softmax + attn write + ctx.
// grid (32, 24), 256 threads, 2 blocks/SM. Thread owns 8 cols (2 float4s at
// j0=tid*4, j1=1024+tid*4). K,V in smem (80KB). Packed f32x2 math over
// COLUMN pairs: q is broadcast-packed per row (q2[r][d] = {q,q}).
// ctx partials via smem (triple-buffered), drained one pair later by 160
// threads, scaled by inv_prev from registers. One barrier per pair.
// ---------------------------------------------------------------------------
#define ATTN_SMEM_FLOATS (10*SQ + 3*10*128 + 2*8*2)
#define ATTN_SMEM_BYTES  (ATTN_SMEM_FLOATS*4)

__global__ __launch_bounds__(256, 2) void attn_kernel(
    const float* __restrict__ bias,
    const float* __restrict__ lam_p,
    float* __restrict__ attn_out)
{
    extern __shared__ float sm[];
    float* Ksm  = sm;                 // [5][2048]
    float* Vsm  = sm + 5*SQ;          // [5][2048]
    float* part = sm + 10*SQ;         // [3][10][128]
    float* redb = part + 3*10*128;    // [2][8] float2

    int bh = blockIdx.y, row0 = blockIdx.x*64;
    int tid = threadIdx.x, lane = tid & 31, wid = tid >> 5;
    float laml = lam_p[0] * 1.4426950408889634f;
    ull lam2 = pack2(laml, laml);

    const float* kg = g_k + (size_t)bh*DK*SQ;
    const float* vg = g_v + (size_t)bh*DK*SQ;
    const float* qg = g_q + ((size_t)bh*SQ + row0)*DK;
    int b = bh / NH, hh = bh % NH;

    for (int i = tid; i < DK*SQ/4; i += 256) {
        ((float4*)Ksm)[i] = ((const float4*)kg)[i];
        ((float4*)Vsm)[i] = ((const float4*)vg)[i];
    }

    const float* bbase = bias     + ((size_t)bh*SQ + row0)*(size_t)SQ;
    float*       abase = attn_out + ((size_t)bh*SQ + row0)*(size_t)SQ;
    int j0 = tid*4, j1 = 1024 + tid*4;

    ull bc[2][4];
    ldcs2(bbase + j0,      bc[0][0], bc[0][1]);
    ldcs2(bbase + j1,      bc[0][2], bc[0][3]);
    ldcs2(bbase + SQ + j0, bc[1][0], bc[1][1]);
    ldcs2(bbase + SQ + j1, bc[1][2], bc[1][3]);

    float inv_prev0 = 0.f, inv_prev1 = 0.f;
    __syncthreads();   // K,V ready

    for (int pair = 0; pair < 32; pair++) {
        int p3 = pair % 3;
        const float* qp = qg + pair*2*DK;
        // q broadcast-packed PER ROW (both packed lanes are columns of the
        // same row) — this was the R4 correctness bug.
        ull q2[2][DK];
        #pragma unroll
        for (int r = 0; r < 2; r++)
            #pragma unroll
            for (int d = 0; d < DK; d++) {
                float qv = qp[r*DK + d];
                q2[r][d] = pack2(qv, qv);
            }

        ull e2[2][4], ce2[2][DK], ls2[2] = {0ull, 0ull};
        #pragma unroll
        for (int r = 0; r < 2; r++)
            #pragma unroll
            for (int d = 0; d < DK; d++) ce2[r][d] = 0ull;

        #pragma unroll
        for (int hf = 0; hf < 2; hf++) {
            int j = hf ? j1 : j0;
            ull kd[DK][2];
            #pragma unroll
            for (int d = 0; d < DK; d++) {
                ulonglong2 t = *(const ulonglong2*)(Ksm + d*SQ + j);
                kd[d][0] = t.x; kd[d][1] = t.y;
            }
            #pragma unroll
            for (int r = 0; r < 2; r++) {
                #pragma unroll
                for (int c = 0; c < 2; c++) {
                    ull s2 = mul2(lam2, bc[r][hf*2+c]);
                    #pragma unroll
                    for (int d = 0; d < DK; d++) s2 = fma2(q2[r][d], kd[d][c], s2);
                    float slo, shi; unpack2(s2, slo, shi);
                    ull e = pack2(ex2a(slo), ex2a(shi));
                    e2[r][hf*2+c] = e;
                    ls2[r] = add2(ls2[r], e);
                }
            }
            ull vd[DK][2];
            #pragma unroll
            for (int d = 0; d < DK; d++) {
                ulonglong2 t = *(const ulonglong2*)(Vsm + d*SQ + j);
                vd[d][0] = t.x; vd[d][1] = t.y;
            }
            #pragma unroll
            for (int r = 0; r < 2; r++)
                #pragma unroll
                for (int c = 0; c < 2; c++)
                    #pragma unroll
                    for (int d = 0; d < DK; d++)
                        ce2[r][d] = fma2(e2[r][hf*2+c], vd[d][c], ce2[r][d]);
        }

        // prefetch next pair's bias (bc fully consumed above)
        {
            int np = (pair < 31) ? pair + 1 : pair;
            const float* bn = bbase + (size_t)(np*2)*SQ;
            ldcs2(bn + j0,      bc[0][0], bc[0][1]);
            ldcs2(bn + j1,      bc[0][2], bc[0][3]);
            ldcs2(bn + SQ + j0, bc[1][0], bc[1][1]);
            ldcs2(bn + SQ + j1, bc[1][2], bc[1][3]);
        }

        // row sums -> warp reduce -> redb (double-buffered)
        float ls0, ls1;
        { float a, bq_; unpack2(ls2[0], a, bq_); ls0 = a + bq_;
          unpack2(ls2[1], a, bq_); ls1 = a + bq_; }
        #pragma unroll
        for (int o = 16; o; o >>= 1) {
            ls0 += __shfl_xor_sync(0xffffffffu, ls0, o);
            ls1 += __shfl_xor_sync(0xffffffffu, ls1, o);
        }
        if (lane == 0) ((float2*)redb)[(pair&1)*8 + wid] = make_float2(ls0, ls1);

        // ctx partials: horizontal + lane-pair reduce + STS (triple buffer)
        #pragma unroll
        for (int r = 0; r < 2; r++)
            #pragma unroll
            for (int d = 0; d < DK; d++) {
                float a, bq_; unpack2(ce2[r][d], a, bq_);
                float s = a + bq_;
                s += __shfl_xor_sync(0xffffffffu, s, 1);
                if (!(lane & 1)) part[(p3*10 + r*5 + d)*128 + (tid >> 1)] = s;
            }

        __syncthreads();   // the ONLY barrier per pair

        float t0 = 0.f, t1 = 0.f;
        {
            const float2* rp = (const float2*)redb + (pair&1)*8;
            #pragma unroll
            for (int w2 = 0; w2 < 8; w2++) { float2 v = rp[w2]; t0 += v.x; t1 += v.y; }
        }
        float inv0 = rcpa(t0), inv1 = rcpa(t1);

        // drain previous pair's ctx partials (race-free: triple buffer)
        if (pair > 0 && tid < 160) {
            int val = tid >> 4, piece = tid & 15;
            int pprev = (p3 == 0) ? 2 : p3 - 1;
            const float4* pp = (const float4*)(part + (pprev*10 + val)*128 + piece*8);
            float4 x = pp[0], y = pp[1];
            float s = ((x.x+x.y)+(x.z+x.w)) + ((y.x+y.y)+(y.z+y.w));
            unsigned m = 0xFFFFu << (lane & 16);
            s += __shfl_xor_sync(m, s, 8); s += __shfl_xor_sync(m, s, 4);
            s += __shfl_xor_sync(m, s, 2); s += __shfl_xor_sync(m, s, 1);
            if (piece == 0) {
                int r = (val >= 5), d = val - r*5;
                float ip = r ? inv_prev1 : inv_prev0;
                g_ctx[((size_t)b*SQ + row0 + (pair-1)*2 + r)*DI + hh*DK + d] = s * ip;
            }
        }

        // normalized attn store
        {
            ull i20 = pack2(inv0, inv0), i21 = pack2(inv1, inv1);
            float* a0 = abase + (size_t)(pair*2)*SQ;
            stcs2(a0 + j0,      mul2(e2[0][0], i20), mul2(e2[0][1], i20));
            stcs2(a0 + j1,      mul2(e2[0][2], i20), mul2(e2[0][3], i20));
            stcs2(a0 + SQ + j0, mul2(e2[1][0], i21), mul2(e2[1][1], i21));
            stcs2(a0 + SQ + j1, mul2(e2[1][2], i21), mul2(e2[1][3], i21));
        }
        inv_prev0 = inv0; inv_prev1 = inv1;
    }

    // final drain: pair 31 partials (p3 = 31%3 = 1); visible via last barrier
    if (tid < 160) {
        int val = tid >> 4, piece = tid & 15;
        const float4* pp = (const float4*)(part + ((31%3)*10 + val)*128 + piece*8);
        float4 x = pp[0], y = pp[1];
        float s = ((x.x+x.y)+(x.z+x.w)) + ((y.x+y.y)+(y.z+y.w));
        unsigned m = 0xFFFFu << (lane & 16);
        s += __shfl_xor_sync(m, s, 8); s += __shfl_xor_sync(m, s, 4);
        s += __shfl_xor_sync(m, s, 2); s += __shfl_xor_sync(m, s, 1);
        if (piece == 0) {
            int r = (val >= 5), d = val - r*5;
            float ip = r ? inv_prev1 : inv_prev0;
            g_ctx[((size_t)b*SQ + row0 + 62 + r)*DI + hh*DK + d] = s * ip;
        }
    }
}

// ---------------------------------------------------------------------------
// Kernel 3: out = residual + ctx @ Wo + bo. Warp-per-row, 16 rows/block.
// ---------------------------------------------------------------------------
__global__ __launch_bounds__(256) void out_kernel(
    const float* __restrict__ Qin, const float* __restrict__ Wo,
    const float* __restrict__ bo, float* __restrict__ out)
{
    __shared__ float Ws[DI*DM];
    __shared__ float bs[DM];
    __shared__ float Cs[16][DI];
    int tid = threadIdx.x;
    int rowbase = blockIdx.x * 16;
    for (int idx = tid; idx < DI*DM; idx += 256) Ws[idx] = Wo[idx];
    if (tid < DM) bs[tid] = bo[tid];
    for (int idx = tid; idx < 16*DI; idx += 256) Cs[idx/DI][idx%DI] = g_ctx[rowbase*DI + idx];
    __syncthreads();

    int w = tid >> 5, lane = tid & 31;
    #pragma unroll
    for (int rr = 0; rr < 2; rr++) {
        int r = w + rr*8;
        int rg = rowbase + r;
        float acc1 = bs[lane]      + Qin[rg*DM + lane];
        float acc2 = bs[lane + 32] + Qin[rg*DM + lane + 32];
        #pragma unroll 10
        for (int o = 0; o < DI; o++) {
            float c = Cs[r][o];
            acc1 = fmaf(c, Ws[o*DM + lane],      acc1);
            acc2 = fmaf(c, Ws[o*DM + lane + 32], acc2);
        }
        out[rg*DM + lane]      = acc1;
        out[rg*DM + lane + 32] = acc2;
    }
}

// ---------------------------------------------------------------------------
extern "C" void kernel_launch(void* const* d_in, const int* in_sizes, int n_in,
                              void* d_out, int out_size)
{
    const float* Q    = (const float*)d_in[0];
    const float* K    = (const float*)d_in[1];
    const float* V    = (const float*)d_in[2];
    const float* bias = (const float*)d_in[3];
    const float* lam  = (const float*)d_in[4];
    const float* Wq   = (const float*)d_in[5];
    const float* bq   = (const float*)d_in[6];
    const float* Wk   = (const float*)d_in[7];
    const float* bk   = (const float*)d_in[8];
    const float* Wv   = (const float*)d_in[9];
    const float* bv   = (const float*)d_in[10];
    const float* Wo   = (const float*)d_in[11];
    const float* bo   = (const float*)d_in[12];

    float* out1 = (float*)d_out;                 // [B,S,64]
    float* attn = out1 + (size_t)BB*SQ*DM;       // [B,H,S,S]

    cudaFuncSetAttribute(attn_kernel, cudaFuncAttributeMaxDynamicSharedMemorySize,
                         ATTN_SMEM_BYTES);

    proj_kernel<<<dim3(BB*SQ/64, 3), 512>>>(Q, K, V, Wq, bq, Wk, bk, Wv, bv);
    attn_kernel<<<dim3(SQ/64, BHN), 256, ATTN_SMEM_BYTES>>>(bias, lam, attn);
    out_kernel<<<BB*SQ/16, 256>>>(Q, Wo, bo, out1);
}